// round 2
// baseline (speedup 1.0000x reference)
#include <cuda_runtime.h>
#include <math.h>

// Problem constants
#define NPG     100        // nodes per graph
#define DEG     16
#define NB      4          // nodes per warp-block in GEMM register tiling
#define NBLK    25         // 100 / NB
#define THREADS 512
#define WARPS   16
#define NGRAPH  512

// Shared memory layout (float offsets)
#define OFF_FSH   0                     // 10000 : feat block / agg2 staging
#define OFF_H1    10000                 // 10000 : agg1 staging then h1
#define OFF_W1T   20000                 // 12800 : W1^T padded [100][128]
#define OFF_W2T   32800                 //  3200 : W2^T padded [100][32]
#define OFF_B1    36000                 //   128 : b1 padded
#define OFF_B2    36128                 //    32 : b2 padded
#define OFF_H2    36160                 //  2000 : h2 [100][20]
#define OFF_SC    38160                 //   128 : scratch (v/y/hg/f/stats)
#define OFF_SRC   38288                 //  1600 ints : local src indices
#define SMEM_FLOATS (38288 + 1600)
#define SMEM_BYTES  (SMEM_FLOATS * 4)

__global__ void __launch_bounds__(THREADS, 1) net_kernel(
    const float* __restrict__ feat, const int* __restrict__ esrc,
    const float* __restrict__ self_feat, const float* __restrict__ x3d,
    const float* __restrict__ W1, const float* __restrict__ b1,
    const float* __restrict__ W2, const float* __restrict__ b2,
    const float* __restrict__ Wv2, const float* __restrict__ Wo2,
    const float* __restrict__ g2, const float* __restrict__ be2,
    const float* __restrict__ Wv3, const float* __restrict__ Wo3,
    const float* __restrict__ g3, const float* __restrict__ be3,
    const float* __restrict__ Wf1, const float* __restrict__ bf1,
    const float* __restrict__ Wf2, const float* __restrict__ bf2,
    float* __restrict__ out)
{
    extern __shared__ float sm[];
    float* fsh  = sm + OFF_FSH;
    float* h1sh = sm + OFF_H1;
    float* w1t  = sm + OFF_W1T;
    float* w2t  = sm + OFF_W2T;
    float* b1sh = sm + OFF_B1;
    float* b2sh = sm + OFF_B2;
    float* h2sh = sm + OFF_H2;
    float* sc   = sm + OFF_SC;
    int*   srcs = (int*)(sm + OFF_SRC);

    const int g    = blockIdx.x;
    const int tid  = threadIdx.x;
    const int lane = tid & 31;
    const int warp = tid >> 5;

    // ---------------- Phase 0: stage everything into SMEM ----------------
    {
        const float4* f4 = (const float4*)(feat + (size_t)g * (NPG * 100));
        float4*       d4 = (float4*)fsh;
        #pragma unroll 4
        for (int i = tid; i < 2500; i += THREADS) d4[i] = f4[i];

        const int4* e4 = (const int4*)(esrc + (size_t)g * (NPG * DEG));
        int4*       s4 = (int4*)srcs;
        const int   nb0 = g * NPG;
        #pragma unroll 1
        for (int i = tid; i < 400; i += THREADS) {
            int4 v = e4[i];
            v.x -= nb0; v.y -= nb0; v.z -= nb0; v.w -= nb0;
            s4[i] = v;
        }
        // zero pad columns only (no overlap with fills -> no extra sync)
        for (int i = tid; i < 2800; i += THREADS) {      // w1t cols 100..127
            int r = i / 28, c = i % 28;
            w1t[r * 128 + 100 + c] = 0.f;
        }
        for (int i = tid; i < 1200; i += THREADS) {      // w2t cols 20..31
            int r = i / 12, c = i % 12;
            w2t[r * 32 + 20 + c] = 0.f;
        }
        // transpose W1 [100,100] -> w1t[i*128+o]
        for (int e = tid; e < 10000; e += THREADS) {
            int o = e / 100, i = e % 100;
            w1t[i * 128 + o] = W1[e];
        }
        // transpose W2 [20,100] -> w2t[i*32+o]
        for (int e = tid; e < 2000; e += THREADS) {
            int o = e / 100, i = e % 100;
            w2t[i * 32 + o] = W2[e];
        }
        for (int i = tid; i < 128; i += THREADS) b1sh[i] = (i < 100) ? b1[i] : 0.f;
        if (tid < 32) b2sh[tid] = (tid < 20) ? b2[tid] : 0.f;
    }
    __syncthreads();

    // ---------------- Phase 1: agg1 (mean of 16 nbrs) + GEMM W1 + relu ----------------
    // warp handles blocks of NB=4 nodes; lane covers feature dims {lane,+32,+64,+96}
    for (int b = warp; b < NBLK; b += WARPS) {
        const int n0 = b * NB;
        #pragma unroll
        for (int nb = 0; nb < NB; nb++) {
            const int n = n0 + nb;
            float a0 = 0.f, a1 = 0.f, a2 = 0.f, a3 = 0.f;
            const int* sp = &srcs[n * DEG];
            #pragma unroll
            for (int j = 0; j < DEG; j++) {
                const int s  = sp[j];           // broadcast LDS
                const int bi = s * 100 + lane;
                a0 += fsh[bi];
                a1 += fsh[bi + 32];
                a2 += fsh[bi + 64];
                if (lane < 4) a3 += fsh[bi + 96];
            }
            float* hr = &h1sh[n * 100];
            hr[lane]      = a0 * 0.0625f;
            hr[lane + 32] = a1 * 0.0625f;
            hr[lane + 64] = a2 * 0.0625f;
            if (lane < 4) hr[lane + 96] = a3 * 0.0625f;
        }
        __syncwarp();
        // register-tiled GEMM: 4 nodes x 4 output chunks
        float acc[NB][4];
        #pragma unroll
        for (int nb = 0; nb < NB; nb++)
            #pragma unroll
            for (int c = 0; c < 4; c++) acc[nb][c] = 0.f;

        #pragma unroll 5
        for (int i2 = 0; i2 < 50; i2++) {
            float2 av[NB];
            #pragma unroll
            for (int nb = 0; nb < NB; nb++)
                av[nb] = *(const float2*)&h1sh[(n0 + nb) * 100 + 2 * i2];
            const int wb = (2 * i2) * 128 + lane;
            const float w00 = w1t[wb],       w01 = w1t[wb + 32];
            const float w02 = w1t[wb + 64],  w03 = w1t[wb + 96];
            const float w10 = w1t[wb + 128], w11 = w1t[wb + 160];
            const float w12 = w1t[wb + 192], w13 = w1t[wb + 224];
            #pragma unroll
            for (int nb = 0; nb < NB; nb++) {
                acc[nb][0] = fmaf(av[nb].x, w00, fmaf(av[nb].y, w10, acc[nb][0]));
                acc[nb][1] = fmaf(av[nb].x, w01, fmaf(av[nb].y, w11, acc[nb][1]));
                acc[nb][2] = fmaf(av[nb].x, w02, fmaf(av[nb].y, w12, acc[nb][2]));
                acc[nb][3] = fmaf(av[nb].x, w03, fmaf(av[nb].y, w13, acc[nb][3]));
            }
        }
        __syncwarp();
        #pragma unroll
        for (int nb = 0; nb < NB; nb++) {
            float* hr = &h1sh[(n0 + nb) * 100];
            hr[lane]      = fmaxf(acc[nb][0] + b1sh[lane],      0.f);
            hr[lane + 32] = fmaxf(acc[nb][1] + b1sh[lane + 32], 0.f);
            hr[lane + 64] = fmaxf(acc[nb][2] + b1sh[lane + 64], 0.f);
            if (lane < 4) hr[lane + 96] = fmaxf(acc[nb][3] + b1sh[lane + 96], 0.f);
        }
    }
    __syncthreads();

    // ---------------- Phase 2: agg2 over h1 + GEMM W2 + relu -> h2 [100,20] ----------------
    for (int b = warp; b < NBLK; b += WARPS) {
        const int n0 = b * NB;
        #pragma unroll
        for (int nb = 0; nb < NB; nb++) {
            const int n = n0 + nb;
            float a0 = 0.f, a1 = 0.f, a2 = 0.f, a3 = 0.f;
            const int* sp = &srcs[n * DEG];
            #pragma unroll
            for (int j = 0; j < DEG; j++) {
                const int s  = sp[j];
                const int bi = s * 100 + lane;
                a0 += h1sh[bi];
                a1 += h1sh[bi + 32];
                a2 += h1sh[bi + 64];
                if (lane < 4) a3 += h1sh[bi + 96];
            }
            float* ar = &fsh[n * 100];   // fsh (feat) is dead: reuse as agg2 staging
            ar[lane]      = a0 * 0.0625f;
            ar[lane + 32] = a1 * 0.0625f;
            ar[lane + 64] = a2 * 0.0625f;
            if (lane < 4) ar[lane + 96] = a3 * 0.0625f;
        }
        __syncwarp();
        float acc2[NB] = {0.f, 0.f, 0.f, 0.f};
        #pragma unroll 5
        for (int i2 = 0; i2 < 50; i2++) {
            float2 av[NB];
            #pragma unroll
            for (int nb = 0; nb < NB; nb++)
                av[nb] = *(const float2*)&fsh[(n0 + nb) * 100 + 2 * i2];
            const float w0 = w2t[(2 * i2) * 32 + lane];
            const float w1 = w2t[(2 * i2) * 32 + 32 + lane];
            #pragma unroll
            for (int nb = 0; nb < NB; nb++)
                acc2[nb] = fmaf(av[nb].x, w0, fmaf(av[nb].y, w1, acc2[nb]));
        }
        if (lane < 20) {
            #pragma unroll
            for (int nb = 0; nb < NB; nb++)
                h2sh[(n0 + nb) * 20 + lane] = fmaxf(acc2[nb] + b2sh[lane], 0.f);
        }
    }
    __syncthreads();

    // ---------------- Phase 3 (warp 0 only): pool + attn2 + attn3 + MLP ----------------
    if (warp == 0) {
        // graph mean-pool -> sc[64..83]
        if (lane < 20) {
            float s = 0.f;
            #pragma unroll 10
            for (int n = 0; n < NPG; n++) s += h2sh[n * 20 + lane];
            sc[64 + lane] = s * 0.01f;
        }
        __syncwarp();

        // ---- cross-attn 2 (length-1 softmax == identity): Z = Wo2 @ (Wv2 @ sf) ----
        {
            float v = 0.f;
            const float4* wv = (const float4*)(Wv2 + lane * 200);
            const float4* xf = (const float4*)(self_feat + (size_t)g * 200);
            #pragma unroll
            for (int j = 0; j < 50; j++) {
                float4 a = wv[j], c = xf[j];
                v = fmaf(a.x, c.x, fmaf(a.y, c.y, fmaf(a.z, c.z, fmaf(a.w, c.w, v))));
            }
            sc[lane] = v;
        }
        __syncwarp();
        float y2 = 0.f;
        if (lane < 20) {
            float z = 0.f;
            #pragma unroll
            for (int l = 0; l < 32; l++) z = fmaf(Wo2[lane * 32 + l], sc[l], z);
            y2 = sc[64 + lane] + z;
            sc[32 + lane] = y2;
        }
        __syncwarp();
        if (lane == 0) {
            float mu = 0.f;
            #pragma unroll
            for (int o = 0; o < 20; o++) mu += sc[32 + o];
            mu *= 0.05f;
            float var = 0.f;
            #pragma unroll
            for (int o = 0; o < 20; o++) { float d = sc[32 + o] - mu; var = fmaf(d, d, var); }
            var *= 0.05f;
            sc[100] = mu;
            sc[101] = 1.f / sqrtf(var + 1e-5f);
        }
        __syncwarp();
        if (lane < 20)
            sc[64 + lane] = (y2 - sc[100]) * sc[101] * g2[lane] + be2[lane];
        __syncwarp();

        // ---- cross-attn 3 ----
        {
            float v = 0.f;
            const float4* wv = (const float4*)(Wv3 + lane * 100);
            const float4* xf = (const float4*)(x3d + (size_t)g * 100);
            #pragma unroll
            for (int j = 0; j < 25; j++) {
                float4 a = wv[j], c = xf[j];
                v = fmaf(a.x, c.x, fmaf(a.y, c.y, fmaf(a.z, c.z, fmaf(a.w, c.w, v))));
            }
            sc[lane] = v;
        }
        __syncwarp();
        float y3 = 0.f;
        if (lane < 20) {
            float z = 0.f;
            #pragma unroll
            for (int l = 0; l < 32; l++) z = fmaf(Wo3[lane * 32 + l], sc[l], z);
            y3 = sc[64 + lane] + z;
            sc[32 + lane] = y3;
        }
        __syncwarp();
        if (lane == 0) {
            float mu = 0.f;
            #pragma unroll
            for (int o = 0; o < 20; o++) mu += sc[32 + o];
            mu *= 0.05f;
            float var = 0.f;
            #pragma unroll
            for (int o = 0; o < 20; o++) { float d = sc[32 + o] - mu; var = fmaf(d, d, var); }
            var *= 0.05f;
            sc[100] = mu;
            sc[101] = 1.f / sqrtf(var + 1e-5f);
        }
        __syncwarp();
        if (lane < 20)
            sc[64 + lane] = (y3 - sc[100]) * sc[101] * g3[lane] + be3[lane];
        __syncwarp();

        // ---- MLP head ----
        if (lane < 10) {
            float f = bf1[lane];
            #pragma unroll
            for (int o = 0; o < 20; o++) f = fmaf(Wf1[lane * 20 + o], sc[64 + o], f);
            sc[84 + lane] = fmaxf(f, 0.f);
        }
        __syncwarp();
        if (lane == 0) {
            float r = bf2[0];
            #pragma unroll
            for (int k = 0; k < 10; k++) r = fmaf(Wf2[k], sc[84 + k], r);
            out[g] = r;
        }
    }
}

extern "C" void kernel_launch(void* const* d_in, const int* in_sizes, int n_in,
                              void* d_out, int out_size)
{
    const float* feat      = (const float*)d_in[0];
    const int*   esrc      = (const int*)  d_in[1];
    // d_in[2] = edge_dst (structurally implied, unused)
    const float* self_feat = (const float*)d_in[3];
    const float* x3d       = (const float*)d_in[4];
    const float* W1  = (const float*)d_in[5];
    const float* b1  = (const float*)d_in[6];
    const float* W2  = (const float*)d_in[7];
    const float* b2  = (const float*)d_in[8];
    // d_in[9]=Wq2, d_in[10]=Wk2 unused (softmax over length-1 axis == 1)
    const float* Wv2 = (const float*)d_in[11];
    const float* Wo2 = (const float*)d_in[12];
    const float* g2  = (const float*)d_in[13];
    const float* be2 = (const float*)d_in[14];
    // d_in[15]=Wq3, d_in[16]=Wk3 unused
    const float* Wv3 = (const float*)d_in[17];
    const float* Wo3 = (const float*)d_in[18];
    const float* g3  = (const float*)d_in[19];
    const float* be3 = (const float*)d_in[20];
    const float* Wf1 = (const float*)d_in[21];
    const float* bf1 = (const float*)d_in[22];
    const float* Wf2 = (const float*)d_in[23];
    const float* bf2 = (const float*)d_in[24];
    float* out = (float*)d_out;

    cudaFuncSetAttribute(net_kernel, cudaFuncAttributeMaxDynamicSharedMemorySize, SMEM_BYTES);
    net_kernel<<<NGRAPH, THREADS, SMEM_BYTES>>>(
        feat, esrc, self_feat, x3d,
        W1, b1, W2, b2,
        Wv2, Wo2, g2, be2,
        Wv3, Wo3, g3, be3,
        Wf1, bf1, Wf2, bf2, out);
}